// round 16
// baseline (speedup 1.0000x reference)
#include <cuda_runtime.h>
#include <cuda_bf16.h>
#include <cuda_fp16.h>
#include <math.h>

#define Bq 4
#define Sq 2048
#define DIN 64
#define Dq 512
#define Hq 8
#define Lq 2
#define NCq 2
#define DKq 64
#define TOPKq 35

#define FLAG_RELU  1
#define FLAG_PE    2
#define FLAG_F32   4
#define FLAG_SPLIT 8

#define NEG_INF (-__int_as_float(0x7f800000))

typedef __nv_bfloat16 bf16;

// ---------------- scratch (device globals; no runtime allocation) ----------------
__device__ float g_h [Bq*Sq*Dq];
__device__ float g_v [Bq*Sq*Dq];
__device__ float g_tmp[Bq*Sq*Dq];
__device__ __half g_scores[(size_t)Bq*Hq*Sq*Sq];   // fp16: 256 MB
__device__ float g_pool[Bq*Dq];
__device__ float g_pe[Sq*Dq];

// bf16 hi/lo split planes
__device__ bf16 g_xh[Bq*Sq*DIN],  g_xl[Bq*Sq*DIN];
__device__ bf16 g_ewh[DIN*Dq],    g_ewl[DIN*Dq];
__device__ bf16 g_wqh[Lq*Dq*Dq],  g_wql[Lq*Dq*Dq];
__device__ bf16 g_wkh[Lq*Dq*Dq],  g_wkl[Lq*Dq*Dq];
__device__ bf16 g_wvh[Lq*Dq*Dq],  g_wvl[Lq*Dq*Dq];
__device__ bf16 g_woh[Lq*Dq*Dq],  g_wol[Lq*Dq*Dq];
__device__ bf16 g_f1h[Lq*Dq*4*Dq], g_f1l[Lq*Dq*4*Dq];
__device__ bf16 g_f2h[Lq*4*Dq*Dq], g_f2l[Lq*4*Dq*Dq];
__device__ bf16 g_hh[Bq*Sq*Dq],  g_hl[Bq*Sq*Dq];
__device__ bf16 g_qh[Bq*Sq*Dq],  g_ql[Bq*Sq*Dq];
__device__ bf16 g_kh[Bq*Sq*Dq],  g_kl[Bq*Sq*Dq];
__device__ bf16 g_aoh[Bq*Sq*Dq], g_aol[Bq*Sq*Dq];
__device__ bf16 g_ffh[Bq*Sq*4*Dq], g_ffl[Bq*Sq*4*Dq];

// ---------------- asm helpers ----------------
__device__ __forceinline__ unsigned sm2u(const void* p) {
    return (unsigned)__cvta_generic_to_shared(p);
}
__device__ __forceinline__ void ldsm_x4(unsigned r[4], unsigned a) {
    asm volatile("ldmatrix.sync.aligned.m8n8.x4.shared.b16 {%0,%1,%2,%3}, [%4];"
        : "=r"(r[0]), "=r"(r[1]), "=r"(r[2]), "=r"(r[3]) : "r"(a));
}
__device__ __forceinline__ void ldsm_x2(unsigned &r0, unsigned &r1, unsigned a) {
    asm volatile("ldmatrix.sync.aligned.m8n8.x2.shared.b16 {%0,%1}, [%2];"
        : "=r"(r0), "=r"(r1) : "r"(a));
}
__device__ __forceinline__ void ldsm_x2t(unsigned &r0, unsigned &r1, unsigned a) {
    asm volatile("ldmatrix.sync.aligned.m8n8.x2.trans.shared.b16 {%0,%1}, [%2];"
        : "=r"(r0), "=r"(r1) : "r"(a));
}
__device__ __forceinline__ void mma16816(float* d, const unsigned a[4], unsigned b0, unsigned b1) {
    asm volatile("mma.sync.aligned.m16n8k16.row.col.f32.bf16.bf16.f32 "
        "{%0,%1,%2,%3}, {%4,%5,%6,%7}, {%8,%9}, {%0,%1,%2,%3};"
        : "+f"(d[0]), "+f"(d[1]), "+f"(d[2]), "+f"(d[3])
        : "r"(a[0]), "r"(a[1]), "r"(a[2]), "r"(a[3]), "r"(b0), "r"(b1));
}
#define CP16(d, s)  asm volatile("cp.async.cg.shared.global [%0], [%1], 16;" :: "r"(d), "l"(s))
#define CP_COMMIT() asm volatile("cp.async.commit_group;")
#define CP_WAIT1()  asm volatile("cp.async.wait_group 1;")
#define CP_WAIT0()  asm volatile("cp.async.wait_group 0;")

// ---------------- consolidated split: fp32 -> (hi, lo) bf16 over 8 tensors ----------------
#define R0 (Bq*Sq*DIN)                 // x
#define R1 (R0 + DIN*Dq)               // emb_w
#define R2 (R1 + Lq*Dq*Dq)             // wq
#define R3 (R2 + Lq*Dq*Dq)             // wk
#define R4 (R3 + Lq*Dq*Dq)             // wv
#define R5 (R4 + Lq*Dq*Dq)             // wo
#define R6 (R5 + Lq*Dq*4*Dq)           // ff1
#define R7 (R6 + Lq*4*Dq*Dq)           // ff2
__global__ void split_all_kernel(
    const float* __restrict__ x,  bf16* __restrict__ xh,  bf16* __restrict__ xl,
    const float* __restrict__ ew, bf16* __restrict__ ewh, bf16* __restrict__ ewl,
    const float* __restrict__ wq, bf16* __restrict__ wqh, bf16* __restrict__ wql,
    const float* __restrict__ wk, bf16* __restrict__ wkh, bf16* __restrict__ wkl,
    const float* __restrict__ wv, bf16* __restrict__ wvh, bf16* __restrict__ wvl,
    const float* __restrict__ wo, bf16* __restrict__ woh, bf16* __restrict__ wol,
    const float* __restrict__ f1, bf16* __restrict__ f1h, bf16* __restrict__ f1l,
    const float* __restrict__ f2, bf16* __restrict__ f2h, bf16* __restrict__ f2l)
{
    int i = (blockIdx.x * blockDim.x + threadIdx.x) * 4;
    if (i >= R7) return;
    const float* src; bf16 *dh, *dl; int off;
    if (i < R0)      { src = x;  dh = xh;  dl = xl;  off = i; }
    else if (i < R1) { src = ew; dh = ewh; dl = ewl; off = i - R0; }
    else if (i < R2) { src = wq; dh = wqh; dl = wql; off = i - R1; }
    else if (i < R3) { src = wk; dh = wkh; dl = wkl; off = i - R2; }
    else if (i < R4) { src = wv; dh = wvh; dl = wvl; off = i - R3; }
    else if (i < R5) { src = wo; dh = woh; dl = wol; off = i - R4; }
    else if (i < R6) { src = f1; dh = f1h; dl = f1l; off = i - R5; }
    else             { src = f2; dh = f2h; dl = f2l; off = i - R6; }
    float4 v = *(const float4*)(src + off);
    __nv_bfloat162 h0 = __floats2bfloat162_rn(v.x, v.y);
    __nv_bfloat162 h1 = __floats2bfloat162_rn(v.z, v.w);
    __nv_bfloat162 l0 = __floats2bfloat162_rn(v.x - __bfloat162float(h0.x),
                                              v.y - __bfloat162float(h0.y));
    __nv_bfloat162 l1 = __floats2bfloat162_rn(v.z - __bfloat162float(h1.x),
                                              v.w - __bfloat162float(h1.y));
    *(__nv_bfloat162*)(dh + off)     = h0;
    *(__nv_bfloat162*)(dh + off + 2) = h1;
    *(__nv_bfloat162*)(dl + off)     = l0;
    *(__nv_bfloat162*)(dl + off + 2) = l1;
}

// ---------------- PE table ----------------
__global__ void pe_kernel(float* __restrict__ pe)
{
    int idx = blockIdx.x * blockDim.x + threadIdx.x;
    if (idx >= Sq * Dq) return;
    int s = idx >> 9, c = idx & 511;
    int half = c >> 1;
    double e = exp((double)(2 * half) * (-9.210340371976184 / 512.0));
    float divf = (float)e;
    float argf = (float)s * divf;
    pe[idx] = (c & 1) ? (float)cos((double)argf) : (float)sin((double)argf);
}

// ---------------- bf16 tensor-core GEMM: C = A @ W + bias (split operands) ----------------
#define ST_AH 0
#define ST_AL 10240
#define ST_BH 20480
#define ST_BL 29184
#define GEMM_SMEM (37888 * 2)

__device__ __forceinline__ void gemm_load_stage(
    unsigned short* sm, int st,
    const bf16* Ahg, const bf16* Alg, const bf16* Bhg, const bf16* Blg,
    int row0, int col0, int k0, int K, int N, int tid)
{
    #pragma unroll
    for (int t = 0; t < 2; t++) {
        int ca = tid + t * 256;
        int arow = ca >> 2, akc = (ca & 3) << 3;
        const bf16* sA = Ahg + (size_t)(row0 + arow) * K + k0 + akc;
        CP16(sm2u(sm + ST_AH + st * 5120 + arow * 40 + akc), sA);
        const bf16* sAl2 = Alg + (size_t)(row0 + arow) * K + k0 + akc;
        CP16(sm2u(sm + ST_AL + st * 5120 + arow * 40 + akc), sAl2);
        int kr = ca >> 4, nc = (ca & 15) << 3;
        const bf16* sB = Bhg + (size_t)(k0 + kr) * N + col0 + nc;
        CP16(sm2u(sm + ST_BH + st * 4352 + kr * 136 + nc), sB);
        const bf16* sBl2 = Blg + (size_t)(k0 + kr) * N + col0 + nc;
        CP16(sm2u(sm + ST_BL + st * 4352 + kr * 136 + nc), sBl2);
    }
}

__global__ void __launch_bounds__(256, 2) gemm_bf16_kernel(
    const bf16* __restrict__ Ahg, const bf16* __restrict__ Alg,
    const bf16* __restrict__ Bhg, const bf16* __restrict__ Blg,
    const float* __restrict__ bias,
    float* __restrict__ C, bf16* __restrict__ Chi, bf16* __restrict__ Clo,
    const float* __restrict__ pe,
    int M, int N, int K, int flags)
{
    extern __shared__ unsigned short sm[];
    int tid = threadIdx.x, lane = tid & 31, wid = tid >> 5;
    int row0 = blockIdx.y * 128, col0 = blockIdx.x * 128;
    int warp_m = wid & 1, warp_n = wid >> 1;

    gemm_load_stage(sm, 0, Ahg, Alg, Bhg, Blg, row0, col0, 0, K, N, tid);
    CP_COMMIT();

    float acc[4][4][4] = {};
    int nslab = K >> 5;
    for (int i = 0; i < nslab; i++) {
        int cur = i & 1;
        bool more = (i + 1) < nslab;
        if (more) {
            gemm_load_stage(sm, cur ^ 1, Ahg, Alg, Bhg, Blg, row0, col0, (i + 1) << 5, K, N, tid);
            CP_COMMIT();
            CP_WAIT1();
        } else {
            CP_WAIT0();
        }
        __syncthreads();

        unsigned short* pAh = sm + ST_AH + cur * 5120;
        unsigned short* pAl = sm + ST_AL + cur * 5120;
        unsigned short* pBh = sm + ST_BH + cur * 4352;
        unsigned short* pBl = sm + ST_BL + cur * 4352;

        #pragma unroll
        for (int kt = 0; kt < 2; kt++) {
            int k16 = kt * 16;
            unsigned ah[4][4], al[4][4];
            int arf = warp_m * 64 + (lane & 15);
            int acf = k16 + (lane >> 4) * 8;
            #pragma unroll
            for (int mi = 0; mi < 4; mi++) {
                ldsm_x4(ah[mi], sm2u(pAh + (arf + mi * 16) * 40 + acf));
                ldsm_x4(al[mi], sm2u(pAl + (arf + mi * 16) * 40 + acf));
            }
            #pragma unroll
            for (int ni = 0; ni < 4; ni++) {
                int bR = k16 + (lane & 15);
                int bC = warp_n * 32 + ni * 8;
                unsigned bh0, bh1, bl0, bl1;
                ldsm_x2t(bh0, bh1, sm2u(pBh + bR * 136 + bC));
                ldsm_x2t(bl0, bl1, sm2u(pBl + bR * 136 + bC));
                #pragma unroll
                for (int mi = 0; mi < 4; mi++) {
                    mma16816(acc[mi][ni], ah[mi], bh0, bh1);
                    mma16816(acc[mi][ni], ah[mi], bl0, bl1);
                    mma16816(acc[mi][ni], al[mi], bh0, bh1);
                }
            }
        }
        __syncthreads();
    }

    // epilogue
    int g = lane >> 2, t = lane & 3;
    #pragma unroll
    for (int mi = 0; mi < 4; mi++) {
        #pragma unroll
        for (int ni = 0; ni < 4; ni++) {
            int r = row0 + warp_m * 64 + mi * 16 + g;
            int c = col0 + warp_n * 32 + ni * 8 + 2 * t;
            float b0 = bias[c], b1 = bias[c + 1];
            float v0 = acc[mi][ni][0] + b0, v1 = acc[mi][ni][1] + b1;
            float v2 = acc[mi][ni][2] + b0, v3 = acc[mi][ni][3] + b1;
            if (flags & FLAG_RELU) {
                v0 = fmaxf(v0, 0.0f); v1 = fmaxf(v1, 0.0f);
                v2 = fmaxf(v2, 0.0f); v3 = fmaxf(v3, 0.0f);
            }
            if (flags & FLAG_PE) {
                const float* p0 = pe + (size_t)(r & (Sq - 1)) * Dq + c;
                const float* p1 = pe + (size_t)((r + 8) & (Sq - 1)) * Dq + c;
                v0 += p0[0]; v1 += p0[1];
                v2 += p1[0]; v3 += p1[1];
            }
            if (flags & FLAG_F32) {
                *(float2*)(C + (size_t)r * N + c)       = make_float2(v0, v1);
                *(float2*)(C + (size_t)(r + 8) * N + c) = make_float2(v2, v3);
            }
            if (flags & FLAG_SPLIT) {
                __nv_bfloat162 h0 = __floats2bfloat162_rn(v0, v1);
                __nv_bfloat162 h1 = __floats2bfloat162_rn(v2, v3);
                __nv_bfloat162 l0 = __floats2bfloat162_rn(v0 - __bfloat162float(h0.x),
                                                          v1 - __bfloat162float(h0.y));
                __nv_bfloat162 l1 = __floats2bfloat162_rn(v2 - __bfloat162float(h1.x),
                                                          v3 - __bfloat162float(h1.y));
                *(__nv_bfloat162*)(Chi + (size_t)r * N + c)       = h0;
                *(__nv_bfloat162*)(Chi + (size_t)(r + 8) * N + c) = h1;
                *(__nv_bfloat162*)(Clo + (size_t)r * N + c)       = l0;
                *(__nv_bfloat162*)(Clo + (size_t)(r + 8) * N + c) = l1;
            }
        }
    }
}

// ---------------- scores: all (b,h), fp16 output ----------------
#define SC_SMEM (36864 * 2)
__global__ void __launch_bounds__(256, 2) scores_kernel(
    const bf16* __restrict__ qh, const bf16* __restrict__ ql,
    const bf16* __restrict__ kh, const bf16* __restrict__ kl,
    __half* __restrict__ scores)
{
    extern __shared__ unsigned short sm[];
    unsigned short* Qh = sm;
    unsigned short* Ql = sm + 9216;
    unsigned short* Kh = sm + 18432;
    unsigned short* Kl = sm + 27648;

    int z = blockIdx.z;
    int b = z >> 3, h = z & 7;
    size_t base = (size_t)b * Sq * Dq + h * DKq;
    int q0 = blockIdx.y * 128, kb0 = blockIdx.x * 128;
    int tid = threadIdx.x, lane = tid & 31, wid = tid >> 5;
    int warp_m = wid & 1, warp_n = wid >> 1;

    #pragma unroll
    for (int t = 0; t < 4; t++) {
        int cq = tid + t * 256;
        int row = cq >> 3, dc = (cq & 7) << 3;
        CP16(sm2u(Qh + row * 72 + dc), qh + base + (size_t)(q0 + row) * Dq + dc);
        CP16(sm2u(Ql + row * 72 + dc), ql + base + (size_t)(q0 + row) * Dq + dc);
        CP16(sm2u(Kh + row * 72 + dc), kh + base + (size_t)(kb0 + row) * Dq + dc);
        CP16(sm2u(Kl + row * 72 + dc), kl + base + (size_t)(kb0 + row) * Dq + dc);
    }
    CP_COMMIT();
    CP_WAIT0();
    __syncthreads();

    float acc[4][4][4] = {};
    #pragma unroll
    for (int kt = 0; kt < 4; kt++) {
        int k16 = kt * 16;
        unsigned ah[4][4], al[4][4];
        int arf = warp_m * 64 + (lane & 15);
        int acf = k16 + (lane >> 4) * 8;
        #pragma unroll
        for (int mi = 0; mi < 4; mi++) {
            ldsm_x4(ah[mi], sm2u(Qh + (arf + mi * 16) * 72 + acf));
            ldsm_x4(al[mi], sm2u(Ql + (arf + mi * 16) * 72 + acf));
        }
        #pragma unroll
        for (int ni = 0; ni < 4; ni++) {
            int bR = warp_n * 32 + ni * 8 + (lane & 7);
            int bC = k16 + ((lane >> 3) & 1) * 8;
            unsigned bh0, bh1, bl0, bl1;
            ldsm_x2(bh0, bh1, sm2u(Kh + bR * 72 + bC));
            ldsm_x2(bl0, bl1, sm2u(Kl + bR * 72 + bC));
            #pragma unroll
            for (int mi = 0; mi < 4; mi++) {
                mma16816(acc[mi][ni], ah[mi], bh0, bh1);
                mma16816(acc[mi][ni], ah[mi], bl0, bl1);
                mma16816(acc[mi][ni], al[mi], bh0, bh1);
            }
        }
    }

    __half* dst = scores + (size_t)z * Sq * Sq;
    int g = lane >> 2, t = lane & 3;
    #pragma unroll
    for (int mi = 0; mi < 4; mi++) {
        #pragma unroll
        for (int ni = 0; ni < 4; ni++) {
            int r = q0 + warp_m * 64 + mi * 16 + g;
            int c = kb0 + warp_n * 32 + ni * 8 + 2 * t;
            *(__half2*)(dst + (size_t)r * Sq + c) =
                __floats2half2_rn(acc[mi][ni][0] * 0.125f, acc[mi][ni][1] * 0.125f);
            *(__half2*)(dst + (size_t)(r + 8) * Sq + c) =
                __floats2half2_rn(acc[mi][ni][2] * 0.125f, acc[mi][ni][3] * 0.125f);
        }
    }
}

// ---------------- top-k: register-resident, no smem staging ----------------
// Each lane owns the contiguous 64-value segment [lane*64, lane*64+64) in registers.
// Values-only semantics (reference discards indices; equal values => equal weights).
#define INS4(xv) \
    if ((xv) > c3) { \
        if ((xv) > c0)      { c3 = c2; c2 = c1; c1 = c0; c0 = (xv); } \
        else if ((xv) > c1) { c3 = c2; c2 = c1; c1 = (xv); } \
        else if ((xv) > c2) { c3 = c2; c2 = (xv); } \
        else                  c3 = (xv); \
    }

__global__ void __launch_bounds__(256) topk_attn_kernel(
    const __half* __restrict__ scores, const float* __restrict__ v,
    bf16* __restrict__ aoh, bf16* __restrict__ aol)
{
    __shared__ float tv[8][TOPKq];
    int w = threadIdx.x >> 5, lane = threadIdx.x & 31;
    int r = blockIdx.x * 8 + w;              // r = (b*H + h)*S + qq
    int qq = r & (Sq - 1);
    int h  = (r >> 11) & 7;
    int b  = r >> 14;
    const __half* src = scores + (size_t)r * Sq + lane * 64;

    // load 64 contiguous halves (128B) -> registers
    float x[64];
    #pragma unroll
    for (int i = 0; i < 8; i++) {
        float4 pk = *(const float4*)(src + i * 8);
        const __half2* hp = (const __half2*)&pk;
        #pragma unroll
        for (int u = 0; u < 4; u++) {
            float2 f = __half22float2(hp[u]);
            x[i * 8 + 2 * u]     = f.x;
            x[i * 8 + 2 * u + 1] = f.y;
        }
    }

    // per-lane top-4 cache
    float c0 = NEG_INF, c1 = NEG_INF, c2 = NEG_INF, c3 = NEG_INF;
    #pragma unroll
    for (int i = 0; i < 64; i++) { INS4(x[i]); }

    float thr = __int_as_float(0x7f800000);   // +inf
    for (int it = 0; it < TOPKq; it++) {
        float best = c0;
        #pragma unroll
        for (int off = 16; off; off >>= 1)
            best = fmaxf(best, __shfl_xor_sync(0xffffffffu, best, off));
        unsigned bm = __ballot_sync(0xffffffffu, c0 == best);
        int wl = __ffs(bm) - 1;
        if (lane == 0) tv[w][it] = best;
        if (lane == wl) {
            thr = c0;
            c0 = c1; c1 = c2; c2 = c3; c3 = NEG_INF;
            if (c0 == NEG_INF) {
                // refill from registers: top-4 of values strictly below thr
                #pragma unroll
                for (int i = 0; i < 64; i++) {
                    float xv = x[i];
                    if (xv < thr) { INS4(xv); }
                }
            }
        }
    }
    __syncwarp();

    // softmax over sorted top-k (max = tv[0])
    float m = tv[w][0];
    float lsum = 0.0f;
    for (int j = lane; j < TOPKq; j += 32) {
        float e = expf(tv[w][j] - m);
        tv[w][j] = e;
        lsum += e;
    }
    __syncwarp();
    #pragma unroll
    for (int off = 16; off; off >>= 1) lsum += __shfl_xor_sync(0xffffffffu, lsum, off);
    float inv = 1.0f / lsum;
    __syncwarp();

    const float* vb = v + (size_t)b * Sq * Dq + h * DKq;
    float a0 = 0.0f, a1 = 0.0f;
    #pragma unroll
    for (int j = 0; j < TOPKq; j++) {
        float a = tv[w][j];
        a0 += a * vb[(size_t)j * Dq + lane];
        a1 += a * vb[(size_t)j * Dq + lane + 32];
    }
    a0 *= inv; a1 *= inv;
    size_t o = (size_t)(b * Sq + qq) * Dq + h * DKq;
    bf16 h0 = __float2bfloat16_rn(a0);
    bf16 h1 = __float2bfloat16_rn(a1);
    aoh[o + lane]      = h0;
    aoh[o + lane + 32] = h1;
    aol[o + lane]      = __float2bfloat16_rn(a0 - __bfloat162float(h0));
    aol[o + lane + 32] = __float2bfloat16_rn(a1 - __bfloat162float(h1));
}

// ---------------- h = LN(h + add), writes fp32 + split ----------------
__global__ void __launch_bounds__(128) add_ln_kernel(
    float* __restrict__ hbuf, const float* __restrict__ add,
    const float* __restrict__ g, const float* __restrict__ bta,
    bf16* __restrict__ hh, bf16* __restrict__ hl)
{
    int row = blockIdx.x;
    int tid = threadIdx.x;
    const float* hr = hbuf + (size_t)row * Dq;
    const float* ar = add  + (size_t)row * Dq;
    float x[4];
    float s = 0.0f, s2 = 0.0f;
    #pragma unroll
    for (int i = 0; i < 4; i++) {
        float v = hr[tid + i * 128] + ar[tid + i * 128];
        x[i] = v; s += v; s2 += v * v;
    }
    __shared__ float rs[4], rs2[4];
    #pragma unroll
    for (int off = 16; off; off >>= 1) {
        s  += __shfl_xor_sync(0xffffffffu, s, off);
        s2 += __shfl_xor_sync(0xffffffffu, s2, off);
    }
    if ((tid & 31) == 0) { rs[tid >> 5] = s; rs2[tid >> 5] = s2; }
    __syncthreads();
    s  = rs[0] + rs[1] + rs[2] + rs[3];
    s2 = rs2[0] + rs2[1] + rs2[2] + rs2[3];
    float mean = s * (1.0f / Dq);
    float var  = s2 * (1.0f / Dq) - mean * mean;
    float invs = rsqrtf(var + 1e-5f);
    float* out = hbuf + (size_t)row * Dq;
    #pragma unroll
    for (int i = 0; i < 4; i++) {
        int c = tid + i * 128;
        float o = (x[i] - mean) * invs * g[c] + bta[c];
        out[c] = o;
        bf16 hi = __float2bfloat16_rn(o);
        hh[(size_t)row * Dq + c] = hi;
        hl[(size_t)row * Dq + c] = __float2bfloat16_rn(o - __bfloat162float(hi));
    }
}

// ---------------- pooled[b,d] = mean_s h[b,s,d] ----------------
__global__ void pool_kernel(const float* __restrict__ h, float* __restrict__ pool)
{
    int idx = blockIdx.x * blockDim.x + threadIdx.x;
    if (idx >= Bq * Dq) return;
    int b = idx >> 9, d = idx & 511;
    const float* p = h + (size_t)b * Sq * Dq + d;
    float s[8] = {};
    for (int i = 0; i < Sq; i += 8) {
        #pragma unroll
        for (int u = 0; u < 8; u++) s[u] += p[(size_t)(i + u) * Dq];
    }
    float t = ((s[0] + s[1]) + (s[2] + s[3])) + ((s[4] + s[5]) + (s[6] + s[7]));
    pool[idx] = t * (1.0f / Sq);
}

// ---------------- decoder: out = relu(pool@W1+b1)@W2+b2 ----------------
__global__ void __launch_bounds__(256) decoder_kernel(
    const float* __restrict__ pool,
    const float* __restrict__ w1, const float* __restrict__ b1,
    const float* __restrict__ w2, const float* __restrict__ b2,
    float* __restrict__ out)
{
    __shared__ float ps[Bq * Dq];
    __shared__ float tmp[Bq * 256];
    int tid = threadIdx.x;
    for (int i = tid; i < Bq * Dq; i += 256) ps[i] = pool[i];
    __syncthreads();
    #pragma unroll
    for (int e = 0; e < 4; e++) {
        int idx = tid + e * 256;
        int bi = idx >> 8, j = idx & 255;
        float acc = b1[j];
        for (int k = 0; k < Dq; k++) acc += ps[bi * Dq + k] * w1[k * 256 + j];
        tmp[idx] = fmaxf(acc, 0.0f);
    }
    __syncthreads();
    if (tid < Bq * NCq) {
        int bi = tid / NCq, c = tid % NCq;
        float acc = b2[c];
        for (int j = 0; j < 256; j++) acc += tmp[bi * 256 + j] * w2[j * NCq + c];
        out[tid] = acc;
    }
}

// ---------------- launch ----------------
extern "C" void kernel_launch(void* const* d_in, const int* in_sizes, int n_in,
                              void* d_out, int out_size)
{
    const float* x      = (const float*)d_in[0];
    const float* emb_w  = (const float*)d_in[1];
    const float* emb_b  = (const float*)d_in[2];
    const float* wq     = (const float*)d_in[3];
    const float* bq     = (const float*)d_in[4];
    const float* wk     = (const float*)d_in[5];
    const float* bk     = (const float*)d_in[6];
    const float* wv     = (const float*)d_in[7];
    const float* bv     = (const float*)d_in[8];
    const float* wo     = (const float*)d_in[9];
    const float* bo     = (const float*)d_in[10];
    const float* ff1_w  = (const float*)d_in[11];
    const float* ff1_b  = (const float*)d_in[12];
    const float* ff2_w  = (const float*)d_in[13];
    const float* ff2_b  = (const float*)d_in[14];
    const float* ln1_g  = (const float*)d_in[15];
    const float* ln1_b  = (const float*)d_in[16];
    const float* ln2_g  = (const float*)d_in[17];
    const float* ln2_b  = (const float*)d_in[18];
    const float* dec1_w = (const float*)d_in[19];
    const float* dec1_b = (const float*)d_in[20];
    const float* dec2_w = (const float*)d_in[21];
    const float* dec2_b = (const float*)d_in[22];
    float* out = (float*)d_out;

    cudaFuncSetAttribute(gemm_bf16_kernel, cudaFuncAttributeMaxDynamicSharedMemorySize, GEMM_SMEM);
    cudaFuncSetAttribute(scores_kernel,    cudaFuncAttributeMaxDynamicSharedMemorySize, SC_SMEM);

    float *h, *v, *tmp, *pl, *pe;
    __half* sc;
    cudaGetSymbolAddress((void**)&h,   g_h);
    cudaGetSymbolAddress((void**)&v,   g_v);
    cudaGetSymbolAddress((void**)&tmp, g_tmp);
    cudaGetSymbolAddress((void**)&sc,  g_scores);
    cudaGetSymbolAddress((void**)&pl,  g_pool);
    cudaGetSymbolAddress((void**)&pe,  g_pe);
    bf16 *xh,*xl,*ewh,*ewl,*wqh,*wql,*wkh,*wkl,*wvh,*wvl,*woh,*wol;
    bf16 *f1h,*f1l,*f2h,*f2l,*hh,*hl,*qh,*ql,*kh,*kl,*aoh,*aol,*ffh,*ffl;
    cudaGetSymbolAddress((void**)&xh,  g_xh);  cudaGetSymbolAddress((void**)&xl,  g_xl);
    cudaGetSymbolAddress((void**)&ewh, g_ewh); cudaGetSymbolAddress((void**)&ewl, g_ewl);
    cudaGetSymbolAddress((void**)&wqh, g_wqh); cudaGetSymbolAddress((void**)&wql, g_wql);
    cudaGetSymbolAddress((void**)&wkh, g_wkh); cudaGetSymbolAddress((void**)&wkl, g_wkl);
    cudaGetSymbolAddress((void**)&wvh, g_wvh); cudaGetSymbolAddress((void**)&wvl, g_wvl);
    cudaGetSymbolAddress((void**)&woh, g_woh); cudaGetSymbolAddress((void**)&wol, g_wol);
    cudaGetSymbolAddress((void**)&f1h, g_f1h); cudaGetSymbolAddress((void**)&f1l, g_f1l);
    cudaGetSymbolAddress((void**)&f2h, g_f2h); cudaGetSymbolAddress((void**)&f2l, g_f2l);
    cudaGetSymbolAddress((void**)&hh,  g_hh);  cudaGetSymbolAddress((void**)&hl,  g_hl);
    cudaGetSymbolAddress((void**)&qh,  g_qh);  cudaGetSymbolAddress((void**)&ql,  g_ql);
    cudaGetSymbolAddress((void**)&kh,  g_kh);  cudaGetSymbolAddress((void**)&kl,  g_kl);
    cudaGetSymbolAddress((void**)&aoh, g_aoh); cudaGetSymbolAddress((void**)&aol, g_aol);
    cudaGetSymbolAddress((void**)&ffh, g_ffh); cudaGetSymbolAddress((void**)&ffl, g_ffl);

    const int M = Bq * Sq;   // 8192

    pe_kernel<<<(Sq * Dq + 255) / 256, 256>>>(pe);
    split_all_kernel<<<(R7/4 + 255)/256, 256>>>(
        x, xh, xl, emb_w, ewh, ewl, wq, wqh, wql, wk, wkh, wkl,
        wv, wvh, wvl, wo, woh, wol, ff1_w, f1h, f1l, ff2_w, f2h, f2l);

    // embedding + PE -> h (fp32) + (hh,hl)
    gemm_bf16_kernel<<<dim3(Dq/128, M/128), 256, GEMM_SMEM>>>(
        xh, xl, ewh, ewl, emb_b, h, hh, hl, pe, M, Dq, DIN, FLAG_PE | FLAG_F32 | FLAG_SPLIT);

    for (int l = 0; l < Lq; l++) {
        size_t woff = (size_t)l * Dq * Dq;
        size_t f1off = (size_t)l * Dq * 4 * Dq;
        size_t f2off = (size_t)l * 4 * Dq * Dq;

        gemm_bf16_kernel<<<dim3(Dq/128, M/128), 256, GEMM_SMEM>>>(
            hh, hl, wqh + woff, wql + woff, bq + l*Dq, nullptr, qh, ql, pe, M, Dq, Dq, FLAG_SPLIT);
        gemm_bf16_kernel<<<dim3(Dq/128, M/128), 256, GEMM_SMEM>>>(
            hh, hl, wkh + woff, wkl + woff, bk + l*Dq, nullptr, kh, kl, pe, M, Dq, Dq, FLAG_SPLIT);
        gemm_bf16_kernel<<<dim3(Dq/128, M/128), 256, GEMM_SMEM>>>(
            hh, hl, wvh + woff, wvl + woff, bv + l*Dq, v, nullptr, nullptr, pe, M, Dq, Dq, FLAG_F32);

        scores_kernel<<<dim3(Sq/128, Sq/128, Bq*Hq), 256, SC_SMEM>>>(qh, ql, kh, kl, sc);
        topk_attn_kernel<<<(Bq*Hq*Sq)/8, 256>>>(sc, v, aoh, aol);

        gemm_bf16_kernel<<<dim3(Dq/128, M/128), 256, GEMM_SMEM>>>(
            aoh, aol, woh + woff, wol + woff, bo + l*Dq, tmp, nullptr, nullptr, pe, M, Dq, Dq, FLAG_F32);
        add_ln_kernel<<<M, 128>>>(h, tmp, ln1_g + l*Dq, ln1_b + l*Dq, hh, hl);

        gemm_bf16_kernel<<<dim3(4*Dq/128, M/128), 256, GEMM_SMEM>>>(
            hh, hl, f1h + f1off, f1l + f1off, ff1_b + l*4*Dq, nullptr, ffh, ffl, pe,
            M, 4*Dq, Dq, FLAG_RELU | FLAG_SPLIT);
        gemm_bf16_kernel<<<dim3(Dq/128, M/128), 256, GEMM_SMEM>>>(
            ffh, ffl, f2h + f2off, f2l + f2off, ff2_b + l*Dq, tmp, nullptr, nullptr, pe,
            M, Dq, 4*Dq, FLAG_F32);
        add_ln_kernel<<<M, 128>>>(h, tmp, ln2_g + l*Dq, ln2_b + l*Dq, hh, hl);
    }

    pool_kernel<<<(Bq * Dq + 255) / 256, 256>>>(h, pl);
    decoder_kernel<<<1, 256>>>(pl, dec1_w, dec1_b, dec2_w, dec2_b, out);
}

// round 17
// speedup vs baseline: 1.2436x; 1.2436x over previous
#include <cuda_runtime.h>
#include <cuda_bf16.h>
#include <cuda_fp16.h>
#include <math.h>

#define Bq 4
#define Sq 2048
#define DIN 64
#define Dq 512
#define Hq 8
#define Lq 2
#define NCq 2
#define DKq 64
#define TOPKq 35

#define FLAG_RELU  1
#define FLAG_PE    2
#define FLAG_F32   4
#define FLAG_SPLIT 8

#define NEG_INF (-__int_as_float(0x7f800000))

typedef __nv_bfloat16 bf16;

// ---------------- scratch (device globals; no runtime allocation) ----------------
__device__ float g_h [Bq*Sq*Dq];
__device__ float g_v [Bq*Sq*Dq];
__device__ float g_tmp[Bq*Sq*Dq];
__device__ __half g_scores[(size_t)Bq*Hq*Sq*Sq];   // fp16: 256 MB
__device__ float g_pool[Bq*Dq];
__device__ float g_pe[Sq*Dq];

// bf16 hi/lo split planes
__device__ bf16 g_xh[Bq*Sq*DIN],  g_xl[Bq*Sq*DIN];
__device__ bf16 g_ewh[DIN*Dq],    g_ewl[DIN*Dq];
__device__ bf16 g_wqh[Lq*Dq*Dq],  g_wql[Lq*Dq*Dq];
__device__ bf16 g_wkh[Lq*Dq*Dq],  g_wkl[Lq*Dq*Dq];
__device__ bf16 g_wvh[Lq*Dq*Dq],  g_wvl[Lq*Dq*Dq];
__device__ bf16 g_woh[Lq*Dq*Dq],  g_wol[Lq*Dq*Dq];
__device__ bf16 g_f1h[Lq*Dq*4*Dq], g_f1l[Lq*Dq*4*Dq];
__device__ bf16 g_f2h[Lq*4*Dq*Dq], g_f2l[Lq*4*Dq*Dq];
__device__ bf16 g_hh[Bq*Sq*Dq],  g_hl[Bq*Sq*Dq];
__device__ bf16 g_qh[Bq*Sq*Dq],  g_ql[Bq*Sq*Dq];
__device__ bf16 g_kh[Bq*Sq*Dq],  g_kl[Bq*Sq*Dq];
__device__ bf16 g_aoh[Bq*Sq*Dq], g_aol[Bq*Sq*Dq];
__device__ bf16 g_ffh[Bq*Sq*4*Dq], g_ffl[Bq*Sq*4*Dq];

// ---------------- asm helpers ----------------
__device__ __forceinline__ unsigned sm2u(const void* p) {
    return (unsigned)__cvta_generic_to_shared(p);
}
__device__ __forceinline__ void ldsm_x4(unsigned r[4], unsigned a) {
    asm volatile("ldmatrix.sync.aligned.m8n8.x4.shared.b16 {%0,%1,%2,%3}, [%4];"
        : "=r"(r[0]), "=r"(r[1]), "=r"(r[2]), "=r"(r[3]) : "r"(a));
}
__device__ __forceinline__ void ldsm_x2(unsigned &r0, unsigned &r1, unsigned a) {
    asm volatile("ldmatrix.sync.aligned.m8n8.x2.shared.b16 {%0,%1}, [%2];"
        : "=r"(r0), "=r"(r1) : "r"(a));
}
__device__ __forceinline__ void ldsm_x2t(unsigned &r0, unsigned &r1, unsigned a) {
    asm volatile("ldmatrix.sync.aligned.m8n8.x2.trans.shared.b16 {%0,%1}, [%2];"
        : "=r"(r0), "=r"(r1) : "r"(a));
}
__device__ __forceinline__ void mma16816(float* d, const unsigned a[4], unsigned b0, unsigned b1) {
    asm volatile("mma.sync.aligned.m16n8k16.row.col.f32.bf16.bf16.f32 "
        "{%0,%1,%2,%3}, {%4,%5,%6,%7}, {%8,%9}, {%0,%1,%2,%3};"
        : "+f"(d[0]), "+f"(d[1]), "+f"(d[2]), "+f"(d[3])
        : "r"(a[0]), "r"(a[1]), "r"(a[2]), "r"(a[3]), "r"(b0), "r"(b1));
}
#define CP16(d, s)  asm volatile("cp.async.cg.shared.global [%0], [%1], 16;" :: "r"(d), "l"(s))
#define CP_COMMIT() asm volatile("cp.async.commit_group;")
#define CP_WAIT1()  asm volatile("cp.async.wait_group 1;")
#define CP_WAIT0()  asm volatile("cp.async.wait_group 0;")

// ---------------- consolidated split: fp32 -> (hi, lo) bf16 over 8 tensors ----------------
#define R0 (Bq*Sq*DIN)                 // x
#define R1 (R0 + DIN*Dq)               // emb_w
#define R2 (R1 + Lq*Dq*Dq)             // wq
#define R3 (R2 + Lq*Dq*Dq)             // wk
#define R4 (R3 + Lq*Dq*Dq)             // wv
#define R5 (R4 + Lq*Dq*Dq)             // wo
#define R6 (R5 + Lq*Dq*4*Dq)           // ff1
#define R7 (R6 + Lq*4*Dq*Dq)           // ff2
__global__ void split_all_kernel(
    const float* __restrict__ x,  bf16* __restrict__ xh,  bf16* __restrict__ xl,
    const float* __restrict__ ew, bf16* __restrict__ ewh, bf16* __restrict__ ewl,
    const float* __restrict__ wq, bf16* __restrict__ wqh, bf16* __restrict__ wql,
    const float* __restrict__ wk, bf16* __restrict__ wkh, bf16* __restrict__ wkl,
    const float* __restrict__ wv, bf16* __restrict__ wvh, bf16* __restrict__ wvl,
    const float* __restrict__ wo, bf16* __restrict__ woh, bf16* __restrict__ wol,
    const float* __restrict__ f1, bf16* __restrict__ f1h, bf16* __restrict__ f1l,
    const float* __restrict__ f2, bf16* __restrict__ f2h, bf16* __restrict__ f2l)
{
    int i = (blockIdx.x * blockDim.x + threadIdx.x) * 4;
    if (i >= R7) return;
    const float* src; bf16 *dh, *dl; int off;
    if (i < R0)      { src = x;  dh = xh;  dl = xl;  off = i; }
    else if (i < R1) { src = ew; dh = ewh; dl = ewl; off = i - R0; }
    else if (i < R2) { src = wq; dh = wqh; dl = wql; off = i - R1; }
    else if (i < R3) { src = wk; dh = wkh; dl = wkl; off = i - R2; }
    else if (i < R4) { src = wv; dh = wvh; dl = wvl; off = i - R3; }
    else if (i < R5) { src = wo; dh = woh; dl = wol; off = i - R4; }
    else if (i < R6) { src = f1; dh = f1h; dl = f1l; off = i - R5; }
    else             { src = f2; dh = f2h; dl = f2l; off = i - R6; }
    float4 v = *(const float4*)(src + off);
    __nv_bfloat162 h0 = __floats2bfloat162_rn(v.x, v.y);
    __nv_bfloat162 h1 = __floats2bfloat162_rn(v.z, v.w);
    __nv_bfloat162 l0 = __floats2bfloat162_rn(v.x - __bfloat162float(h0.x),
                                              v.y - __bfloat162float(h0.y));
    __nv_bfloat162 l1 = __floats2bfloat162_rn(v.z - __bfloat162float(h1.x),
                                              v.w - __bfloat162float(h1.y));
    *(__nv_bfloat162*)(dh + off)     = h0;
    *(__nv_bfloat162*)(dh + off + 2) = h1;
    *(__nv_bfloat162*)(dl + off)     = l0;
    *(__nv_bfloat162*)(dl + off + 2) = l1;
}

// ---------------- PE table ----------------
__global__ void pe_kernel(float* __restrict__ pe)
{
    int idx = blockIdx.x * blockDim.x + threadIdx.x;
    if (idx >= Sq * Dq) return;
    int s = idx >> 9, c = idx & 511;
    int half = c >> 1;
    double e = exp((double)(2 * half) * (-9.210340371976184 / 512.0));
    float divf = (float)e;
    float argf = (float)s * divf;
    pe[idx] = (c & 1) ? (float)cos((double)argf) : (float)sin((double)argf);
}

// ---------------- bf16 tensor-core GEMM: C = A @ W + bias (split operands) ----------------
#define ST_AH 0
#define ST_AL 10240
#define ST_BH 20480
#define ST_BL 29184
#define GEMM_SMEM (37888 * 2)

__device__ __forceinline__ void gemm_load_stage(
    unsigned short* sm, int st,
    const bf16* Ahg, const bf16* Alg, const bf16* Bhg, const bf16* Blg,
    int row0, int col0, int k0, int K, int N, int tid)
{
    #pragma unroll
    for (int t = 0; t < 2; t++) {
        int ca = tid + t * 256;
        int arow = ca >> 2, akc = (ca & 3) << 3;
        const bf16* sA = Ahg + (size_t)(row0 + arow) * K + k0 + akc;
        CP16(sm2u(sm + ST_AH + st * 5120 + arow * 40 + akc), sA);
        const bf16* sAl2 = Alg + (size_t)(row0 + arow) * K + k0 + akc;
        CP16(sm2u(sm + ST_AL + st * 5120 + arow * 40 + akc), sAl2);
        int kr = ca >> 4, nc = (ca & 15) << 3;
        const bf16* sB = Bhg + (size_t)(k0 + kr) * N + col0 + nc;
        CP16(sm2u(sm + ST_BH + st * 4352 + kr * 136 + nc), sB);
        const bf16* sBl2 = Blg + (size_t)(k0 + kr) * N + col0 + nc;
        CP16(sm2u(sm + ST_BL + st * 4352 + kr * 136 + nc), sBl2);
    }
}

__global__ void __launch_bounds__(256, 2) gemm_bf16_kernel(
    const bf16* __restrict__ Ahg, const bf16* __restrict__ Alg,
    const bf16* __restrict__ Bhg, const bf16* __restrict__ Blg,
    const float* __restrict__ bias,
    float* __restrict__ C, bf16* __restrict__ Chi, bf16* __restrict__ Clo,
    const float* __restrict__ pe,
    int M, int N, int K, int flags)
{
    extern __shared__ unsigned short sm[];
    int tid = threadIdx.x, lane = tid & 31, wid = tid >> 5;
    int row0 = blockIdx.y * 128, col0 = blockIdx.x * 128;
    int warp_m = wid & 1, warp_n = wid >> 1;

    gemm_load_stage(sm, 0, Ahg, Alg, Bhg, Blg, row0, col0, 0, K, N, tid);
    CP_COMMIT();

    float acc[4][4][4] = {};
    int nslab = K >> 5;
    for (int i = 0; i < nslab; i++) {
        int cur = i & 1;
        bool more = (i + 1) < nslab;
        if (more) {
            gemm_load_stage(sm, cur ^ 1, Ahg, Alg, Bhg, Blg, row0, col0, (i + 1) << 5, K, N, tid);
            CP_COMMIT();
            CP_WAIT1();
        } else {
            CP_WAIT0();
        }
        __syncthreads();

        unsigned short* pAh = sm + ST_AH + cur * 5120;
        unsigned short* pAl = sm + ST_AL + cur * 5120;
        unsigned short* pBh = sm + ST_BH + cur * 4352;
        unsigned short* pBl = sm + ST_BL + cur * 4352;

        #pragma unroll
        for (int kt = 0; kt < 2; kt++) {
            int k16 = kt * 16;
            unsigned ah[4][4], al[4][4];
            int arf = warp_m * 64 + (lane & 15);
            int acf = k16 + (lane >> 4) * 8;
            #pragma unroll
            for (int mi = 0; mi < 4; mi++) {
                ldsm_x4(ah[mi], sm2u(pAh + (arf + mi * 16) * 40 + acf));
                ldsm_x4(al[mi], sm2u(pAl + (arf + mi * 16) * 40 + acf));
            }
            #pragma unroll
            for (int ni = 0; ni < 4; ni++) {
                int bR = k16 + (lane & 15);
                int bC = warp_n * 32 + ni * 8;
                unsigned bh0, bh1, bl0, bl1;
                ldsm_x2t(bh0, bh1, sm2u(pBh + bR * 136 + bC));
                ldsm_x2t(bl0, bl1, sm2u(pBl + bR * 136 + bC));
                #pragma unroll
                for (int mi = 0; mi < 4; mi++) {
                    mma16816(acc[mi][ni], ah[mi], bh0, bh1);
                    mma16816(acc[mi][ni], ah[mi], bl0, bl1);
                    mma16816(acc[mi][ni], al[mi], bh0, bh1);
                }
            }
        }
        __syncthreads();
    }

    // epilogue
    int g = lane >> 2, t = lane & 3;
    #pragma unroll
    for (int mi = 0; mi < 4; mi++) {
        #pragma unroll
        for (int ni = 0; ni < 4; ni++) {
            int r = row0 + warp_m * 64 + mi * 16 + g;
            int c = col0 + warp_n * 32 + ni * 8 + 2 * t;
            float b0 = bias[c], b1 = bias[c + 1];
            float v0 = acc[mi][ni][0] + b0, v1 = acc[mi][ni][1] + b1;
            float v2 = acc[mi][ni][2] + b0, v3 = acc[mi][ni][3] + b1;
            if (flags & FLAG_RELU) {
                v0 = fmaxf(v0, 0.0f); v1 = fmaxf(v1, 0.0f);
                v2 = fmaxf(v2, 0.0f); v3 = fmaxf(v3, 0.0f);
            }
            if (flags & FLAG_PE) {
                const float* p0 = pe + (size_t)(r & (Sq - 1)) * Dq + c;
                const float* p1 = pe + (size_t)((r + 8) & (Sq - 1)) * Dq + c;
                v0 += p0[0]; v1 += p0[1];
                v2 += p1[0]; v3 += p1[1];
            }
            if (flags & FLAG_F32) {
                *(float2*)(C + (size_t)r * N + c)       = make_float2(v0, v1);
                *(float2*)(C + (size_t)(r + 8) * N + c) = make_float2(v2, v3);
            }
            if (flags & FLAG_SPLIT) {
                __nv_bfloat162 h0 = __floats2bfloat162_rn(v0, v1);
                __nv_bfloat162 h1 = __floats2bfloat162_rn(v2, v3);
                __nv_bfloat162 l0 = __floats2bfloat162_rn(v0 - __bfloat162float(h0.x),
                                                          v1 - __bfloat162float(h0.y));
                __nv_bfloat162 l1 = __floats2bfloat162_rn(v2 - __bfloat162float(h1.x),
                                                          v3 - __bfloat162float(h1.y));
                *(__nv_bfloat162*)(Chi + (size_t)r * N + c)       = h0;
                *(__nv_bfloat162*)(Chi + (size_t)(r + 8) * N + c) = h1;
                *(__nv_bfloat162*)(Clo + (size_t)r * N + c)       = l0;
                *(__nv_bfloat162*)(Clo + (size_t)(r + 8) * N + c) = l1;
            }
        }
    }
}

// ---------------- scores: all (b,h), fp16 output ----------------
#define SC_SMEM (36864 * 2)
__global__ void __launch_bounds__(256, 2) scores_kernel(
    const bf16* __restrict__ qh, const bf16* __restrict__ ql,
    const bf16* __restrict__ kh, const bf16* __restrict__ kl,
    __half* __restrict__ scores)
{
    extern __shared__ unsigned short sm[];
    unsigned short* Qh = sm;
    unsigned short* Ql = sm + 9216;
    unsigned short* Kh = sm + 18432;
    unsigned short* Kl = sm + 27648;

    int z = blockIdx.z;
    int b = z >> 3, h = z & 7;
    size_t base = (size_t)b * Sq * Dq + h * DKq;
    int q0 = blockIdx.y * 128, kb0 = blockIdx.x * 128;
    int tid = threadIdx.x, lane = tid & 31, wid = tid >> 5;
    int warp_m = wid & 1, warp_n = wid >> 1;

    #pragma unroll
    for (int t = 0; t < 4; t++) {
        int cq = tid + t * 256;
        int row = cq >> 3, dc = (cq & 7) << 3;
        CP16(sm2u(Qh + row * 72 + dc), qh + base + (size_t)(q0 + row) * Dq + dc);
        CP16(sm2u(Ql + row * 72 + dc), ql + base + (size_t)(q0 + row) * Dq + dc);
        CP16(sm2u(Kh + row * 72 + dc), kh + base + (size_t)(kb0 + row) * Dq + dc);
        CP16(sm2u(Kl + row * 72 + dc), kl + base + (size_t)(kb0 + row) * Dq + dc);
    }
    CP_COMMIT();
    CP_WAIT0();
    __syncthreads();

    float acc[4][4][4] = {};
    #pragma unroll
    for (int kt = 0; kt < 4; kt++) {
        int k16 = kt * 16;
        unsigned ah[4][4], al[4][4];
        int arf = warp_m * 64 + (lane & 15);
        int acf = k16 + (lane >> 4) * 8;
        #pragma unroll
        for (int mi = 0; mi < 4; mi++) {
            ldsm_x4(ah[mi], sm2u(Qh + (arf + mi * 16) * 72 + acf));
            ldsm_x4(al[mi], sm2u(Ql + (arf + mi * 16) * 72 + acf));
        }
        #pragma unroll
        for (int ni = 0; ni < 4; ni++) {
            int bR = warp_n * 32 + ni * 8 + (lane & 7);
            int bC = k16 + ((lane >> 3) & 1) * 8;
            unsigned bh0, bh1, bl0, bl1;
            ldsm_x2(bh0, bh1, sm2u(Kh + bR * 72 + bC));
            ldsm_x2(bl0, bl1, sm2u(Kl + bR * 72 + bC));
            #pragma unroll
            for (int mi = 0; mi < 4; mi++) {
                mma16816(acc[mi][ni], ah[mi], bh0, bh1);
                mma16816(acc[mi][ni], ah[mi], bl0, bl1);
                mma16816(acc[mi][ni], al[mi], bh0, bh1);
            }
        }
    }

    __half* dst = scores + (size_t)z * Sq * Sq;
    int g = lane >> 2, t = lane & 3;
    #pragma unroll
    for (int mi = 0; mi < 4; mi++) {
        #pragma unroll
        for (int ni = 0; ni < 4; ni++) {
            int r = q0 + warp_m * 64 + mi * 16 + g;
            int c = kb0 + warp_n * 32 + ni * 8 + 2 * t;
            *(__half2*)(dst + (size_t)r * Sq + c) =
                __floats2half2_rn(acc[mi][ni][0] * 0.125f, acc[mi][ni][1] * 0.125f);
            *(__half2*)(dst + (size_t)(r + 8) * Sq + c) =
                __floats2half2_rn(acc[mi][ni][2] * 0.125f, acc[mi][ni][3] * 0.125f);
        }
    }
}

// ---------------- top-k (R14 version): smem-staged, 4 warps/block ----------------
__global__ void __launch_bounds__(128) topk_attn_kernel(
    const __half* __restrict__ scores, const float* __restrict__ v,
    bf16* __restrict__ aoh, bf16* __restrict__ aol)
{
    __shared__ float srow[4][Sq];
    __shared__ float tv[4][TOPKq];
    int w = threadIdx.x >> 5, lane = threadIdx.x & 31;
    int r = blockIdx.x * 4 + w;              // r = (b*H + h)*S + qq
    int qq = r & (Sq - 1);
    int h  = (r >> 11) & 7;
    int b  = r >> 14;
    const __half* src = scores + (size_t)r * Sq;
    float* my = &srow[w][0];
    for (int i = lane; i < Sq / 8; i += 32) {
        float4 pk4 = *(const float4*)(src + i * 8);   // 8 halves
        const __half2* hp = (const __half2*)&pk4;
        #pragma unroll
        for (int u = 0; u < 4; u++) {
            float2 f = __half22float2(hp[u]);
            my[i * 8 + 2 * u]     = f.x;
            my[i * 8 + 2 * u + 1] = f.y;
        }
    }
    __syncwarp();

    float c0 = NEG_INF, c1 = NEG_INF, c2 = NEG_INF, c3 = NEG_INF;
    #pragma unroll
    for (int i = 0; i < 64; i++) {
        float x = my[i * 32 + lane];
        if (x > c3) {
            if (x > c0)      { c3 = c2; c2 = c1; c1 = c0; c0 = x; }
            else if (x > c1) { c3 = c2; c2 = c1; c1 = x; }
            else if (x > c2) { c3 = c2; c2 = x; }
            else               c3 = x;
        }
    }

    float thr = __int_as_float(0x7f800000);   // +inf
    for (int it = 0; it < TOPKq; it++) {
        float best = c0;
        #pragma unroll
        for (int off = 16; off; off >>= 1)
            best = fmaxf(best, __shfl_xor_sync(0xffffffffu, best, off));
        unsigned bm = __ballot_sync(0xffffffffu, c0 == best);
        int wl = __ffs(bm) - 1;
        if (lane == 0) tv[w][it] = best;
        if (lane == wl) {
            thr = c0;
            c0 = c1; c1 = c2; c2 = c3; c3 = NEG_INF;
            if (c0 == NEG_INF) {
                for (int i = 0; i < 64; i++) {
                    float x = my[i * 32 + lane];
                    if (x < thr && x > c3) {
                        if (x > c0)      { c3 = c2; c2 = c1; c1 = c0; c0 = x; }
                        else if (x > c1) { c3 = c2; c2 = c1; c1 = x; }
                        else if (x > c2) { c3 = c2; c2 = x; }
                        else               c3 = x;
                    }
                }
            }
        }
    }
    __syncwarp();

    float m = tv[w][0];
    float lsum = 0.0f;
    for (int j = lane; j < TOPKq; j += 32) {
        float e = expf(tv[w][j] - m);
        tv[w][j] = e;
        lsum += e;
    }
    __syncwarp();
    #pragma unroll
    for (int off = 16; off; off >>= 1) lsum += __shfl_xor_sync(0xffffffffu, lsum, off);
    float inv = 1.0f / lsum;
    __syncwarp();

    const float* vb = v + (size_t)b * Sq * Dq + h * DKq;
    float a0 = 0.0f, a1 = 0.0f;
    #pragma unroll
    for (int j = 0; j < TOPKq; j++) {
        float a = tv[w][j];
        a0 += a * vb[(size_t)j * Dq + lane];
        a1 += a * vb[(size_t)j * Dq + lane + 32];
    }
    a0 *= inv; a1 *= inv;
    size_t o = (size_t)(b * Sq + qq) * Dq + h * DKq;
    bf16 h0 = __float2bfloat16_rn(a0);
    bf16 h1 = __float2bfloat16_rn(a1);
    aoh[o + lane]      = h0;
    aoh[o + lane + 32] = h1;
    aol[o + lane]      = __float2bfloat16_rn(a0 - __bfloat162float(h0));
    aol[o + lane + 32] = __float2bfloat16_rn(a1 - __bfloat162float(h1));
}

// ---------------- h = LN(h + add), writes fp32 + split ----------------
__global__ void __launch_bounds__(128) add_ln_kernel(
    float* __restrict__ hbuf, const float* __restrict__ add,
    const float* __restrict__ g, const float* __restrict__ bta,
    bf16* __restrict__ hh, bf16* __restrict__ hl)
{
    int row = blockIdx.x;
    int tid = threadIdx.x;
    const float* hr = hbuf + (size_t)row * Dq;
    const float* ar = add  + (size_t)row * Dq;
    float x[4];
    float s = 0.0f, s2 = 0.0f;
    #pragma unroll
    for (int i = 0; i < 4; i++) {
        float v = hr[tid + i * 128] + ar[tid + i * 128];
        x[i] = v; s += v; s2 += v * v;
    }
    __shared__ float rs[4], rs2[4];
    #pragma unroll
    for (int off = 16; off; off >>= 1) {
        s  += __shfl_xor_sync(0xffffffffu, s, off);
        s2 += __shfl_xor_sync(0xffffffffu, s2, off);
    }
    if ((tid & 31) == 0) { rs[tid >> 5] = s; rs2[tid >> 5] = s2; }
    __syncthreads();
    s  = rs[0] + rs[1] + rs[2] + rs[3];
    s2 = rs2[0] + rs2[1] + rs2[2] + rs2[3];
    float mean = s * (1.0f / Dq);
    float var  = s2 * (1.0f / Dq) - mean * mean;
    float invs = rsqrtf(var + 1e-5f);
    float* out = hbuf + (size_t)row * Dq;
    #pragma unroll
    for (int i = 0; i < 4; i++) {
        int c = tid + i * 128;
        float o = (x[i] - mean) * invs * g[c] + bta[c];
        out[c] = o;
        bf16 hi = __float2bfloat16_rn(o);
        hh[(size_t)row * Dq + c] = hi;
        hl[(size_t)row * Dq + c] = __float2bfloat16_rn(o - __bfloat162float(hi));
    }
}

// ---------------- pooled[b,d] = mean_s h[b,s,d] ----------------
__global__ void pool_kernel(const float* __restrict__ h, float* __restrict__ pool)
{
    int idx = blockIdx.x * blockDim.x + threadIdx.x;
    if (idx >= Bq * Dq) return;
    int b = idx >> 9, d = idx & 511;
    const float* p = h + (size_t)b * Sq * Dq + d;
    float s[8] = {};
    for (int i = 0; i < Sq; i += 8) {
        #pragma unroll
        for (int u = 0; u < 8; u++) s[u] += p[(size_t)(i + u) * Dq];
    }
    float t = ((s[0] + s[1]) + (s[2] + s[3])) + ((s[4] + s[5]) + (s[6] + s[7]));
    pool[idx] = t * (1.0f / Sq);
}

// ---------------- decoder: out = relu(pool@W1+b1)@W2+b2 ----------------
__global__ void __launch_bounds__(256) decoder_kernel(
    const float* __restrict__ pool,
    const float* __restrict__ w1, const float* __restrict__ b1,
    const float* __restrict__ w2, const float* __restrict__ b2,
    float* __restrict__ out)
{
    __shared__ float ps[Bq * Dq];
    __shared__ float tmp[Bq * 256];
    int tid = threadIdx.x;
    for (int i = tid; i < Bq * Dq; i += 256) ps[i] = pool[i];
    __syncthreads();
    #pragma unroll
    for (int e = 0; e < 4; e++) {
        int idx = tid + e * 256;
        int bi = idx >> 8, j = idx & 255;
        float acc = b1[j];
        for (int k = 0; k < Dq; k++) acc += ps[bi * Dq + k] * w1[k * 256 + j];
        tmp[idx] = fmaxf(acc, 0.0f);
    }
    __syncthreads();
    if (tid < Bq * NCq) {
        int bi = tid / NCq, c = tid % NCq;
        float acc = b2[c];
        for (int j = 0; j < 256; j++) acc += tmp[bi * 256 + j] * w2[j * NCq + c];
        out[tid] = acc;
    }
}

// ---------------- launch ----------------
extern "C" void kernel_launch(void* const* d_in, const int* in_sizes, int n_in,
                              void* d_out, int out_size)
{
    const float* x      = (const float*)d_in[0];
    const float* emb_w  = (const float*)d_in[1];
    const float* emb_b  = (const float*)d_in[2];
    const float* wq     = (const float*)d_in[3];
    const float* bq     = (const float*)d_in[4];
    const float* wk     = (const float*)d_in[5];
    const float* bk     = (const float*)d_in[6];
    const float* wv     = (const float*)d_in[7];
    const float* bv     = (const float*)d_in[8];
    const float* wo     = (const float*)d_in[9];
    const float* bo     = (const float*)d_in[10];
    const float* ff1_w  = (const float*)d_in[11];
    const float* ff1_b  = (const float*)d_in[12];
    const float* ff2_w  = (const float*)d_in[13];
    const float* ff2_b  = (const float*)d_in[14];
    const float* ln1_g  = (const float*)d_in[15];
    const float* ln1_b  = (const float*)d_in[16];
    const float* ln2_g  = (const float*)d_in[17];
    const float* ln2_b  = (const float*)d_in[18];
    const float* dec1_w = (const float*)d_in[19];
    const float* dec1_b = (const float*)d_in[20];
    const float* dec2_w = (const float*)d_in[21];
    const float* dec2_b = (const float*)d_in[22];
    float* out = (float*)d_out;

    cudaFuncSetAttribute(gemm_bf16_kernel, cudaFuncAttributeMaxDynamicSharedMemorySize, GEMM_SMEM);
    cudaFuncSetAttribute(scores_kernel,    cudaFuncAttributeMaxDynamicSharedMemorySize, SC_SMEM);

    float *h, *v, *tmp, *pl, *pe;
    __half* sc;
    cudaGetSymbolAddress((void**)&h,   g_h);
    cudaGetSymbolAddress((void**)&v,   g_v);
    cudaGetSymbolAddress((void**)&tmp, g_tmp);
    cudaGetSymbolAddress((void**)&sc,  g_scores);
    cudaGetSymbolAddress((void**)&pl,  g_pool);
    cudaGetSymbolAddress((void**)&pe,  g_pe);
    bf16 *xh,*xl,*ewh,*ewl,*wqh,*wql,*wkh,*wkl,*wvh,*wvl,*woh,*wol;
    bf16 *f1h,*f1l,*f2h,*f2l,*hh,*hl,*qh,*ql,*kh,*kl,*aoh,*aol,*ffh,*ffl;
    cudaGetSymbolAddress((void**)&xh,  g_xh);  cudaGetSymbolAddress((void**)&xl,  g_xl);
    cudaGetSymbolAddress((void**)&ewh, g_ewh); cudaGetSymbolAddress((void**)&ewl, g_ewl);
    cudaGetSymbolAddress((void**)&wqh, g_wqh); cudaGetSymbolAddress((void**)&wql, g_wql);
    cudaGetSymbolAddress((void**)&wkh, g_wkh); cudaGetSymbolAddress((void**)&wkl, g_wkl);
    cudaGetSymbolAddress((void**)&wvh, g_wvh); cudaGetSymbolAddress((void**)&wvl, g_wvl);
    cudaGetSymbolAddress((void**)&woh, g_woh); cudaGetSymbolAddress((void**)&wol, g_wol);
    cudaGetSymbolAddress((void**)&f1h, g_f1h); cudaGetSymbolAddress((void**)&f1l, g_f1l);
    cudaGetSymbolAddress((void**)&f2h, g_f2h); cudaGetSymbolAddress((void**)&f2l, g_f2l);
    cudaGetSymbolAddress((void**)&hh,  g_hh);  cudaGetSymbolAddress((void**)&hl,  g_hl);
    cudaGetSymbolAddress((void**)&qh,  g_qh);  cudaGetSymbolAddress((void**)&ql,  g_ql);
    cudaGetSymbolAddress((void**)&kh,  g_kh);  cudaGetSymbolAddress((void**)&kl,  g_kl);
    cudaGetSymbolAddress((void**)&aoh, g_aoh); cudaGetSymbolAddress((void**)&aol, g_aol);
    cudaGetSymbolAddress((void**)&ffh, g_ffh); cudaGetSymbolAddress((void**)&ffl, g_ffl);

    const int M = Bq * Sq;   // 8192

    pe_kernel<<<(Sq * Dq + 255) / 256, 256>>>(pe);
    split_all_kernel<<<(R7/4 + 255)/256, 256>>>(
        x, xh, xl, emb_w, ewh, ewl, wq, wqh, wql, wk, wkh, wkl,
        wv, wvh, wvl, wo, woh, wol, ff1_w, f1h, f1l, ff2_w, f2h, f2l);

    // embedding + PE -> h (fp32) + (hh,hl)
    gemm_bf16_kernel<<<dim3(Dq/128, M/128), 256, GEMM_SMEM>>>(
        xh, xl, ewh, ewl, emb_b, h, hh, hl, pe, M, Dq, DIN, FLAG_PE | FLAG_F32 | FLAG_SPLIT);

    for (int l = 0; l < Lq; l++) {
        size_t woff = (size_t)l * Dq * Dq;
        size_t f1off = (size_t)l * Dq * 4 * Dq;
        size_t f2off = (size_t)l * 4 * Dq * Dq;

        gemm_bf16_kernel<<<dim3(Dq/128, M/128), 256, GEMM_SMEM>>>(
            hh, hl, wqh + woff, wql + woff, bq + l*Dq, nullptr, qh, ql, pe, M, Dq, Dq, FLAG_SPLIT);
        gemm_bf16_kernel<<<dim3(Dq/128, M/128), 256, GEMM_SMEM>>>(
            hh, hl, wkh + woff, wkl + woff, bk + l*Dq, nullptr, kh, kl, pe, M, Dq, Dq, FLAG_SPLIT);
        gemm_bf16_kernel<<<dim3(Dq/128, M/128), 256, GEMM_SMEM>>>(
            hh, hl, wvh + woff, wvl + woff, bv + l*Dq, v, nullptr, nullptr, pe, M, Dq, Dq, FLAG_F32);

        scores_kernel<<<dim3(Sq/128, Sq/128, Bq*Hq), 256, SC_SMEM>>>(qh, ql, kh, kl, sc);
        topk_attn_kernel<<<(Bq*Hq*Sq)/4, 128>>>(sc, v, aoh, aol);

        gemm_bf16_kernel<<<dim3(Dq/128, M/128), 256, GEMM_SMEM>>>(
            aoh, aol, woh + woff, wol + woff, bo + l*Dq, tmp, nullptr, nullptr, pe, M, Dq, Dq, FLAG_F32);
        add_ln_kernel<<<M, 128>>>(h, tmp, ln1_g + l*Dq, ln1_b + l*Dq, hh, hl);

        gemm_bf16_kernel<<<dim3(4*Dq/128, M/128), 256, GEMM_SMEM>>>(
            hh, hl, f1h + f1off, f1l + f1off, ff1_b + l*4*Dq, nullptr, ffh, ffl, pe,
            M, 4*Dq, Dq, FLAG_RELU | FLAG_SPLIT);
        gemm_bf16_kernel<<<dim3(Dq/128, M/128), 256, GEMM_SMEM>>>(
            ffh, ffl, f2h + f2off, f2l + f2off, ff2_b + l*Dq, tmp, nullptr, nullptr, pe,
            M, Dq, 4*Dq, FLAG_F32);
        add_ln_kernel<<<M, 128>>>(h, tmp, ln2_g + l*Dq, ln2_b + l*Dq, hh, hl);
    }

    pool_kernel<<<(Bq * Dq + 255) / 256, 256>>>(h, pl);
    decoder_kernel<<<1, 256>>>(pl, dec1_w, dec1_b, dec2_w, dec2_b, out);
}